// round 4
// baseline (speedup 1.0000x reference)
#include <cuda_runtime.h>
#include <cuda_fp16.h>

#define NN 50000
#define EE 800000
#define TE 850000          // EE + NN self-loops
#define GEMMB 444          // gemm1 blocks (3/SM * 148)
#define NSCAN 49           // ceil(NN/1024)

typedef unsigned long long ull;

// ---------------- scratch (static device globals; zero-initialized) --------------
__device__ unsigned g_h1h[NN * 64];   // layer-1 linear output, fp16 (128 half/row)
__device__ float g_as1[NN * 8];
__device__ float g_ad1[NN * 8];
__device__ float g_h2[NN * 16];
__device__ float g_as2[NN];
__device__ float g_ad2[NN];
__device__ int   g_deg[NN];           // zero at entry of every call (invariant)
__device__ int   g_rowptr[NN + 1];
__device__ int   g_cursor[NN];
__device__ int   g_col[TE];
__device__ int   g_bsum[NSCAN];
__device__ int   g_arrive;            // monotonic epoch ticket counter

// ---------------- packed f32x2 helpers (sm_100+ FFMA2) ----------------
__device__ __forceinline__ ull ffma2(ull a, ull b, ull c) {
    ull d;
    asm("fma.rn.f32x2 %0, %1, %2, %3;" : "=l"(d) : "l"(a), "l"(b), "l"(c));
    return d;
}
__device__ __forceinline__ ull packdup(float x) {
    ull v;
    asm("mov.b64 %0, {%1, %1};" : "=l"(v) : "f"(x));
    return v;
}
__device__ __forceinline__ float2 unpack2(ull v) {
    float2 f;
    asm("mov.b64 {%0, %1}, %2;" : "=f"(f.x), "=f"(f.y) : "l"(v));
    return f;
}

// ---------------- gemm1: h1 = x @ W1 + per-head alpha reductions -----------------
__global__ void __launch_bounds__(128) k_gemm1(
    const float* __restrict__ x, const float* __restrict__ W1,
    const float* __restrict__ asw, const float* __restrict__ adw)
{
    extern __shared__ float sm[];
    float* Ws = sm;            // 128*128
    float* xs = sm + 16384;    // 8*128
    int tid = threadIdx.x, lane = tid & 31, w = tid >> 5;

    for (int i = tid; i < 16384; i += 128) Ws[i] = W1[i];
    float4 aws = ((const float4*)asw)[lane];
    float4 awd = ((const float4*)adw)[lane];
    __syncthreads();

    for (int chunk = blockIdx.x; chunk < NN / 8; chunk += GEMMB) {
        int base = chunk * 8;
        for (int i = tid; i < 1024; i += 128) xs[i] = x[base * 128 + i];
        __syncthreads();

        int r0 = 2 * w;
        const float* x0p = xs + r0 * 128;
        const float* x1p = x0p + 128;
        ull a00 = 0, a01 = 0, a10 = 0, a11 = 0;
        #pragma unroll 4
        for (int k = 0; k < 128; k++) {
            ulonglong2 wv = *(const ulonglong2*)(Ws + k * 128 + lane * 4);
            ull xp0 = packdup(x0p[k]);
            ull xp1 = packdup(x1p[k]);
            a00 = ffma2(xp0, wv.x, a00);
            a01 = ffma2(xp0, wv.y, a01);
            a10 = ffma2(xp1, wv.x, a10);
            a11 = ffma2(xp1, wv.y, a11);
        }
        #pragma unroll
        for (int rr = 0; rr < 2; rr++) {
            float2 lo = unpack2(rr == 0 ? a00 : a10);
            float2 hi = unpack2(rr == 0 ? a01 : a11);
            int g = base + r0 + rr;
            __half2 p0 = __floats2half2_rn(lo.x, lo.y);
            __half2 p1 = __floats2half2_rn(hi.x, hi.y);
            uint2 u;
            u.x = *reinterpret_cast<unsigned*>(&p0);
            u.y = *reinterpret_cast<unsigned*>(&p1);
            ((uint2*)g_h1h)[g * 32 + lane] = u;
            float ps = lo.x * aws.x + lo.y * aws.y + hi.x * aws.z + hi.y * aws.w;
            float pd = lo.x * awd.x + lo.y * awd.y + hi.x * awd.z + hi.y * awd.w;
            ps += __shfl_xor_sync(0xFFFFFFFFu, ps, 1);
            ps += __shfl_xor_sync(0xFFFFFFFFu, ps, 2);
            pd += __shfl_xor_sync(0xFFFFFFFFu, pd, 1);
            pd += __shfl_xor_sync(0xFFFFFFFFu, pd, 2);
            if ((lane & 3) == 0) {
                g_as1[g * 8 + (lane >> 2)] = ps;
                g_ad1[g * 8 + (lane >> 2)] = pd;
            }
        }
        __syncthreads();
    }
}

// ---------------- degree histogram (side stream) ---------------------------------
__global__ void __launch_bounds__(256) k_deg(const int* __restrict__ ei) {
    int t = blockIdx.x * blockDim.x + threadIdx.x;
    if (t < EE / 4) {
        int4 d = ((const int4*)(ei + EE))[t];
        atomicAdd(&g_deg[d.x], 1);
        atomicAdd(&g_deg[d.y], 1);
        atomicAdd(&g_deg[d.z], 1);
        atomicAdd(&g_deg[d.w], 1);
    }
}

// ---------------- single-kernel exclusive scan (49 resident blocks) --------------
// epoch-ticket grid barrier: g_arrive grows by exactly NSCAN per call (monotonic,
// deterministic across graph replays).
__global__ void __launch_bounds__(1024) k_scanall() {
    __shared__ int warpsums[32];
    __shared__ int sb[NSCAN];
    __shared__ int s_boff;
    int t = threadIdx.x, lane = t & 31, wid = t >> 5;
    int b = blockIdx.x;
    int i = b * 1024 + t;
    int v = (i < NN) ? g_deg[i] + 1 : 0;    // +1 = self-loop

    // block-local inclusive scan
    int x = v;
    #pragma unroll
    for (int o = 1; o < 32; o <<= 1) {
        int y = __shfl_up_sync(0xFFFFFFFFu, x, o);
        if (lane >= o) x += y;
    }
    if (lane == 31) warpsums[wid] = x;
    __syncthreads();
    if (wid == 0) {
        int w2 = warpsums[lane];
        #pragma unroll
        for (int o = 1; o < 32; o <<= 1) {
            int y = __shfl_up_sync(0xFFFFFFFFu, w2, o);
            if (lane >= o) w2 += y;
        }
        warpsums[lane] = w2;
    }
    __syncthreads();
    int tot = warpsums[31];

    // publish block sum, grid barrier (epoch ticket)
    if (t == 0) {
        g_bsum[b] = tot;
        __threadfence();
        int ticket = atomicAdd(&g_arrive, 1);
        int target = (ticket / NSCAN + 1) * NSCAN;
        while (*((volatile int*)&g_arrive) < target) { }
        __threadfence();
    }
    __syncthreads();

    // all block sums now visible: compute this block's offset
    if (t < NSCAN) sb[t] = *((volatile int*)&g_bsum[t]);
    __syncthreads();
    if (t == 0) {
        int run = 0;
        for (int j = 0; j < b; j++) run += sb[j];
        s_boff = run;
        if (b == NSCAN - 1) {
            int all = run + sb[b];
            g_rowptr[NN] = all;     // == TE
        }
    }
    __syncthreads();

    int excl = x - v + (wid > 0 ? warpsums[wid - 1] : 0) + s_boff;
    if (i < NN) {
        g_rowptr[i] = excl;
        g_cursor[i] = excl;
        g_deg[i] = 0;               // restore invariant for next call
    }
}

// ---------------- scatter edges into CSR (by destination), int4-vectorized -------
__global__ void __launch_bounds__(256) k_scatter(const int* __restrict__ ei) {
    int t = blockIdx.x * blockDim.x + threadIdx.x;
    const int Q = EE / 4;   // 200000
    if (t < Q) {
        int4 s4 = ((const int4*)ei)[t];
        int4 d4 = ((const int4*)(ei + EE))[t];
        g_col[atomicAdd(&g_cursor[d4.x], 1)] = s4.x;
        g_col[atomicAdd(&g_cursor[d4.y], 1)] = s4.y;
        g_col[atomicAdd(&g_cursor[d4.z], 1)] = s4.z;
        g_col[atomicAdd(&g_cursor[d4.w], 1)] = s4.w;
    } else {
        int n = t - Q;
        if (n < NN) g_col[atomicAdd(&g_cursor[n], 1)] = n;   // self-loop
    }
}

// ---------------- fused: layer-1 aggregation + ELU + layer-2 linear + alphas -----
// One warp per dst node; lane covers channels 4*lane..4*lane+3. After softmax
// aggregation + bias + ELU, hout lives in 4 regs/lane -> compute h2 = hout @ W2
// via padded-smem transpose reduction. Writes h2, as2, ad2. No hout in gmem.
__global__ void __launch_bounds__(256) k_agg1g2(
    const float* __restrict__ b1, const float* __restrict__ W2,
    const float* __restrict__ as2w, const float* __restrict__ ad2w)
{
    __shared__ float Ws2[128 * 16];
    __shared__ float s_a2[32];             // [0:16) a_src2, [16:32) a_dst2
    __shared__ float red[8][32][17];       // padded transpose buffer
    int tid = threadIdx.x, lane = tid & 31, w = tid >> 5;

    for (int i = tid; i < 2048; i += 256) Ws2[i] = W2[i];
    if (tid < 16) { s_a2[tid] = as2w[tid]; s_a2[16 + tid] = ad2w[tid]; }
    __syncthreads();

    int d = blockIdx.x * 8 + w;            // node id (one warp per node)
    if (d >= NN) return;
    int head = lane >> 2;
    int beg = g_rowptr[d], end = g_rowptr[d + 1];
    float adv = g_ad1[d * 8 + head];
    const uint2* h1v = (const uint2*)g_h1h;

    float4 acc = make_float4(0.f, 0.f, 0.f, 0.f);
    float den = 0.f;
    #pragma unroll 2
    for (int j = beg; j < end; j++) {
        int s = g_col[j];
        float e = g_as1[s * 8 + head] + adv;
        e = e > 0.f ? e : 0.2f * e;
        float ex = __expf(e);
        den += ex;
        uint2 hv = h1v[s * 32 + lane];
        float2 f0 = __half22float2(*reinterpret_cast<__half2*>(&hv.x));
        float2 f1 = __half22float2(*reinterpret_cast<__half2*>(&hv.y));
        acc.x += ex * f0.x; acc.y += ex * f0.y;
        acc.z += ex * f1.x; acc.w += ex * f1.y;
    }
    float inv = 1.f / (den + 1e-16f);
    float4 bv = ((const float4*)b1)[lane];
    float4 o;
    o.x = acc.x * inv + bv.x; o.x = o.x > 0.f ? o.x : expm1f(o.x);
    o.y = acc.y * inv + bv.y; o.y = o.y > 0.f ? o.y : expm1f(o.y);
    o.z = acc.z * inv + bv.z; o.z = o.z > 0.f ? o.z : expm1f(o.z);
    o.w = acc.w * inv + bv.w; o.w = o.w > 0.f ? o.w : expm1f(o.w);

    // ---- fused gemm2: p[c] = sum over this lane's 4 k-rows of W2 ----
    float4 p[4];                           // 16 outputs as 4x float4
    {
        const float4* r0 = (const float4*)(Ws2 + (4 * lane + 0) * 16);
        const float4* r1 = (const float4*)(Ws2 + (4 * lane + 1) * 16);
        const float4* r2 = (const float4*)(Ws2 + (4 * lane + 2) * 16);
        const float4* r3 = (const float4*)(Ws2 + (4 * lane + 3) * 16);
        #pragma unroll
        for (int q = 0; q < 4; q++) {
            float4 w0 = r0[q], w1 = r1[q], w2 = r2[q], w3 = r3[q];
            p[q].x = o.x * w0.x + o.y * w1.x + o.z * w2.x + o.w * w3.x;
            p[q].y = o.x * w0.y + o.y * w1.y + o.z * w2.y + o.w * w3.y;
            p[q].z = o.x * w0.z + o.y * w1.z + o.z * w2.z + o.w * w3.z;
            p[q].w = o.x * w0.w + o.y * w1.w + o.z * w2.w + o.w * w3.w;
        }
    }
    // transpose-reduce over 32 lanes via padded smem
    float* row = &red[w][lane][0];
    #pragma unroll
    for (int q = 0; q < 4; q++) {
        row[4 * q + 0] = p[q].x; row[4 * q + 1] = p[q].y;
        row[4 * q + 2] = p[q].z; row[4 * q + 3] = p[q].w;
    }
    __syncwarp();
    int c = lane & 15;                     // lanes 16-31 duplicate channels 0-15
    float h2 = 0.f;
    #pragma unroll 8
    for (int l = 0; l < 32; l++) h2 += red[w][l][c];

    // layer-2 alphas: sum over the 16 channels (reduce within each 16-lane half)
    float ps = h2 * s_a2[c], pd = h2 * s_a2[16 + c];
    #pragma unroll
    for (int off = 8; off; off >>= 1) {
        ps += __shfl_xor_sync(0xFFFFFFFFu, ps, off);
        pd += __shfl_xor_sync(0xFFFFFFFFu, pd, off);
    }
    if (lane < 16) g_h2[d * 16 + lane] = h2;
    if (lane == 0) { g_as2[d] = ps; g_ad2[d] = pd; }
}

// ---------------- layer 2 aggregation -> output ----------------------------------
__global__ void __launch_bounds__(256) k_agg2(const float* __restrict__ b2,
                                              float* __restrict__ out) {
    int t = blockIdx.x * blockDim.x + threadIdx.x;
    int node = t >> 4, c = t & 15;
    if (node >= NN) return;
    int beg = g_rowptr[node], end = g_rowptr[node + 1];
    float adv = g_ad2[node];
    float acc = 0.f, den = 0.f;
    for (int j = beg; j < end; j++) {
        int s = g_col[j];
        float e = g_as2[s] + adv;
        e = e > 0.f ? e : 0.2f * e;
        float ex = __expf(e);
        den += ex;
        acc += ex * g_h2[s * 16 + c];
    }
    out[node * 16 + c] = acc / (den + 1e-16f) + b2[c];
}

// ---------------- launch (fork/join: CSR build overlaps gemm1) -------------------
extern "C" void kernel_launch(void* const* d_in, const int* in_sizes, int n_in,
                              void* d_out, int out_size) {
    const float* x    = (const float*)d_in[0];
    const int*   ei   = (const int*)d_in[1];
    const float* W1   = (const float*)d_in[2];
    const float* as1w = (const float*)d_in[3];
    const float* ad1w = (const float*)d_in[4];
    const float* b1   = (const float*)d_in[5];
    const float* W2   = (const float*)d_in[6];
    const float* as2w = (const float*)d_in[7];
    const float* ad2w = (const float*)d_in[8];
    const float* b2   = (const float*)d_in[9];
    float* out = (float*)d_out;

    static cudaStream_t s2 = nullptr;
    static cudaEvent_t evFork = nullptr, evJoin = nullptr;
    if (!s2) {
        cudaStreamCreateWithFlags(&s2, cudaStreamNonBlocking);
        cudaEventCreateWithFlags(&evFork, cudaEventDisableTiming);
        cudaEventCreateWithFlags(&evJoin, cudaEventDisableTiming);
        cudaFuncSetAttribute(k_gemm1, cudaFuncAttributeMaxDynamicSharedMemorySize, 69632);
    }

    // fork: side stream builds the CSR while the main stream runs gemm1
    cudaEventRecord(evFork, 0);
    cudaStreamWaitEvent(s2, evFork, 0);

    k_gemm1<<<GEMMB, 128, 69632>>>(x, W1, as1w, ad1w);

    k_deg<<<(EE / 4 + 255) / 256, 256, 0, s2>>>(ei);
    k_scanall<<<NSCAN, 1024, 0, s2>>>();
    k_scatter<<<(EE / 4 + NN + 255) / 256, 256, 0, s2>>>(ei);

    // join
    cudaEventRecord(evJoin, s2);
    cudaStreamWaitEvent(0, evJoin, 0);

    // fused layer-1 aggregation + layer-2 linear
    k_agg1g2<<<(NN + 7) / 8, 256>>>(b1, W2, as2w, ad2w);

    // layer-2 aggregation -> output
    k_agg2<<<(NN * 16 + 255) / 256, 256>>>(b2, out);
}

// round 5
// speedup vs baseline: 1.0052x; 1.0052x over previous
#include <cuda_runtime.h>
#include <cuda_fp16.h>

#define NN 50000
#define EE 800000
#define TE 850000          // EE + NN self-loops
#define DEGB 96            // blocks of fused kernel doing degree counting
#define GEMMB 444          // blocks of fused kernel doing gemm1 (3/SM * 148)
#define NSCAN 49           // ceil(NN/1024)

typedef unsigned long long ull;

// ---------------- scratch (static device globals; zero-initialized) --------------
__device__ unsigned g_h1h[NN * 64];   // layer-1 linear output, fp16 (128 half/row)
__device__ float g_as1[NN * 8];
__device__ float g_ad1[NN * 8];
__device__ float g_h2[NN * 16];
__device__ float g_as2[NN];
__device__ float g_ad2[NN];
__device__ int   g_deg[NN];           // zero at entry of every call (invariant)
__device__ int   g_rowptr[NN + 1];
__device__ int   g_cursor[NN];
__device__ int   g_col[TE];
__device__ int   g_bsum[NSCAN];
__device__ int   g_arrive;            // monotonic epoch ticket counter

// ---------------- packed f32x2 helpers (sm_100+ FFMA2) ----------------
__device__ __forceinline__ ull ffma2(ull a, ull b, ull c) {
    ull d;
    asm("fma.rn.f32x2 %0, %1, %2, %3;" : "=l"(d) : "l"(a), "l"(b), "l"(c));
    return d;
}
__device__ __forceinline__ ull packdup(float x) {
    ull v;
    asm("mov.b64 %0, {%1, %1};" : "=l"(v) : "f"(x));
    return v;
}
__device__ __forceinline__ float2 unpack2(ull v) {
    float2 f;
    asm("mov.b64 {%0, %1}, %2;" : "=f"(f.x), "=f"(f.y) : "l"(v));
    return f;
}

// ---------------- fused: degree histogram (blocks 0..DEGB) + gemm1 (rest) --------
__global__ void __launch_bounds__(128) k_fused1(
    const float* __restrict__ x, const float* __restrict__ W1,
    const float* __restrict__ asw, const float* __restrict__ adw,
    const int* __restrict__ ei)
{
    extern __shared__ float sm[];
    if (blockIdx.x < DEGB) {
        const int nt = DEGB * 128;
        int t = blockIdx.x * 128 + threadIdx.x;
        const int4* dsts = (const int4*)(ei + EE);
        for (int i = t; i < EE / 4; i += nt) {
            int4 d = dsts[i];
            atomicAdd(&g_deg[d.x], 1);
            atomicAdd(&g_deg[d.y], 1);
            atomicAdd(&g_deg[d.z], 1);
            atomicAdd(&g_deg[d.w], 1);
        }
        return;
    }
    float* Ws = sm;            // 128*128
    float* xs = sm + 16384;    // 8*128
    int tid = threadIdx.x, lane = tid & 31, w = tid >> 5;

    for (int i = tid; i < 16384; i += 128) Ws[i] = W1[i];
    float4 aws = ((const float4*)asw)[lane];
    float4 awd = ((const float4*)adw)[lane];
    __syncthreads();

    int bid = blockIdx.x - DEGB;
    for (int chunk = bid; chunk < NN / 8; chunk += GEMMB) {
        int base = chunk * 8;
        for (int i = tid; i < 1024; i += 128) xs[i] = x[base * 128 + i];
        __syncthreads();

        int r0 = 2 * w;
        const float* x0p = xs + r0 * 128;
        const float* x1p = x0p + 128;
        ull a00 = 0, a01 = 0, a10 = 0, a11 = 0;
        #pragma unroll 4
        for (int k = 0; k < 128; k++) {
            ulonglong2 wv = *(const ulonglong2*)(Ws + k * 128 + lane * 4);
            ull xp0 = packdup(x0p[k]);
            ull xp1 = packdup(x1p[k]);
            a00 = ffma2(xp0, wv.x, a00);
            a01 = ffma2(xp0, wv.y, a01);
            a10 = ffma2(xp1, wv.x, a10);
            a11 = ffma2(xp1, wv.y, a11);
        }
        #pragma unroll
        for (int rr = 0; rr < 2; rr++) {
            float2 lo = unpack2(rr == 0 ? a00 : a10);
            float2 hi = unpack2(rr == 0 ? a01 : a11);
            int g = base + r0 + rr;
            __half2 p0 = __floats2half2_rn(lo.x, lo.y);
            __half2 p1 = __floats2half2_rn(hi.x, hi.y);
            uint2 u;
            u.x = *reinterpret_cast<unsigned*>(&p0);
            u.y = *reinterpret_cast<unsigned*>(&p1);
            ((uint2*)g_h1h)[g * 32 + lane] = u;
            float ps = lo.x * aws.x + lo.y * aws.y + hi.x * aws.z + hi.y * aws.w;
            float pd = lo.x * awd.x + lo.y * awd.y + hi.x * awd.z + hi.y * awd.w;
            ps += __shfl_xor_sync(0xFFFFFFFFu, ps, 1);
            ps += __shfl_xor_sync(0xFFFFFFFFu, ps, 2);
            pd += __shfl_xor_sync(0xFFFFFFFFu, pd, 1);
            pd += __shfl_xor_sync(0xFFFFFFFFu, pd, 2);
            if ((lane & 3) == 0) {
                g_as1[g * 8 + (lane >> 2)] = ps;
                g_ad1[g * 8 + (lane >> 2)] = pd;
            }
        }
        __syncthreads();
    }
}

// ---------------- single-kernel exclusive scan (49 resident blocks) --------------
// Launched on an otherwise-idle device => all blocks co-resident, barrier safe.
__global__ void __launch_bounds__(1024) k_scanall() {
    __shared__ int warpsums[32];
    __shared__ int sb[NSCAN];
    __shared__ int s_boff;
    int t = threadIdx.x, lane = t & 31, wid = t >> 5;
    int b = blockIdx.x;
    int i = b * 1024 + t;
    int v = (i < NN) ? g_deg[i] + 1 : 0;    // +1 = self-loop

    int x = v;
    #pragma unroll
    for (int o = 1; o < 32; o <<= 1) {
        int y = __shfl_up_sync(0xFFFFFFFFu, x, o);
        if (lane >= o) x += y;
    }
    if (lane == 31) warpsums[wid] = x;
    __syncthreads();
    if (wid == 0) {
        int w2 = warpsums[lane];
        #pragma unroll
        for (int o = 1; o < 32; o <<= 1) {
            int y = __shfl_up_sync(0xFFFFFFFFu, w2, o);
            if (lane >= o) w2 += y;
        }
        warpsums[lane] = w2;
    }
    __syncthreads();
    int tot = warpsums[31];

    // publish block sum, epoch-ticket grid barrier (monotonic => replay-safe)
    if (t == 0) {
        g_bsum[b] = tot;
        __threadfence();
        int ticket = atomicAdd(&g_arrive, 1);
        int target = (ticket / NSCAN + 1) * NSCAN;
        while (*((volatile int*)&g_arrive) < target) { }
        __threadfence();
    }
    __syncthreads();

    if (t < NSCAN) sb[t] = *((volatile int*)&g_bsum[t]);
    __syncthreads();
    if (t == 0) {
        int run = 0;
        for (int j = 0; j < b; j++) run += sb[j];
        s_boff = run;
        if (b == NSCAN - 1) g_rowptr[NN] = run + sb[b];   // == TE
    }
    __syncthreads();

    int excl = x - v + (wid > 0 ? warpsums[wid - 1] : 0) + s_boff;
    if (i < NN) {
        g_rowptr[i] = excl;
        g_cursor[i] = excl;
        g_deg[i] = 0;               // restore invariant for next call
    }
}

// ---------------- scatter edges into CSR (by destination), int4-vectorized -------
__global__ void __launch_bounds__(256) k_scatter(const int* __restrict__ ei) {
    int t = blockIdx.x * blockDim.x + threadIdx.x;
    const int Q = EE / 4;   // 200000
    if (t < Q) {
        int4 s4 = ((const int4*)ei)[t];
        int4 d4 = ((const int4*)(ei + EE))[t];
        g_col[atomicAdd(&g_cursor[d4.x], 1)] = s4.x;
        g_col[atomicAdd(&g_cursor[d4.y], 1)] = s4.y;
        g_col[atomicAdd(&g_cursor[d4.z], 1)] = s4.z;
        g_col[atomicAdd(&g_cursor[d4.w], 1)] = s4.w;
    } else {
        int n = t - Q;
        if (n < NN) g_col[atomicAdd(&g_cursor[n], 1)] = n;   // self-loop
    }
}

// ---------------- fused: layer-1 aggregation + ELU + layer-2 linear + alphas -----
// One warp per dst node; lane covers channels 4*lane..4*lane+3. After softmax
// aggregation + bias + ELU, hout lives in 4 regs/lane -> h2 = hout @ W2 via
// padded-smem transpose reduction. Writes h2, as2, ad2. No hout in gmem.
__global__ void __launch_bounds__(256) k_agg1g2(
    const float* __restrict__ b1, const float* __restrict__ W2,
    const float* __restrict__ as2w, const float* __restrict__ ad2w)
{
    __shared__ float Ws2[128 * 16];
    __shared__ float s_a2[32];             // [0:16) a_src2, [16:32) a_dst2
    __shared__ float red[8][32][17];       // padded transpose buffer
    int tid = threadIdx.x, lane = tid & 31, w = tid >> 5;

    for (int i = tid; i < 2048; i += 256) Ws2[i] = W2[i];
    if (tid < 16) { s_a2[tid] = as2w[tid]; s_a2[16 + tid] = ad2w[tid]; }
    __syncthreads();

    int d = blockIdx.x * 8 + w;            // node id (one warp per node)
    if (d >= NN) return;
    int head = lane >> 2;
    int beg = g_rowptr[d], end = g_rowptr[d + 1];
    float adv = g_ad1[d * 8 + head];
    const uint2* h1v = (const uint2*)g_h1h;

    float4 acc = make_float4(0.f, 0.f, 0.f, 0.f);
    float den = 0.f;
    #pragma unroll 2
    for (int j = beg; j < end; j++) {
        int s = g_col[j];
        float e = g_as1[s * 8 + head] + adv;
        e = e > 0.f ? e : 0.2f * e;
        float ex = __expf(e);
        den += ex;
        uint2 hv = h1v[s * 32 + lane];
        float2 f0 = __half22float2(*reinterpret_cast<__half2*>(&hv.x));
        float2 f1 = __half22float2(*reinterpret_cast<__half2*>(&hv.y));
        acc.x += ex * f0.x; acc.y += ex * f0.y;
        acc.z += ex * f1.x; acc.w += ex * f1.y;
    }
    float inv = 1.f / (den + 1e-16f);
    float4 bv = ((const float4*)b1)[lane];
    float4 o;
    o.x = acc.x * inv + bv.x; o.x = o.x > 0.f ? o.x : expm1f(o.x);
    o.y = acc.y * inv + bv.y; o.y = o.y > 0.f ? o.y : expm1f(o.y);
    o.z = acc.z * inv + bv.z; o.z = o.z > 0.f ? o.z : expm1f(o.z);
    o.w = acc.w * inv + bv.w; o.w = o.w > 0.f ? o.w : expm1f(o.w);

    // ---- fused gemm2: partials over this lane's 4 k-rows of W2 ----
    float4 p[4];                           // 16 outputs as 4x float4
    {
        const float4* r0 = (const float4*)(Ws2 + (4 * lane + 0) * 16);
        const float4* r1 = (const float4*)(Ws2 + (4 * lane + 1) * 16);
        const float4* r2 = (const float4*)(Ws2 + (4 * lane + 2) * 16);
        const float4* r3 = (const float4*)(Ws2 + (4 * lane + 3) * 16);
        #pragma unroll
        for (int q = 0; q < 4; q++) {
            float4 w0 = r0[q], w1 = r1[q], w2 = r2[q], w3 = r3[q];
            p[q].x = o.x * w0.x + o.y * w1.x + o.z * w2.x + o.w * w3.x;
            p[q].y = o.x * w0.y + o.y * w1.y + o.z * w2.y + o.w * w3.y;
            p[q].z = o.x * w0.z + o.y * w1.z + o.z * w2.z + o.w * w3.z;
            p[q].w = o.x * w0.w + o.y * w1.w + o.z * w2.w + o.w * w3.w;
        }
    }
    // transpose-reduce over 32 lanes via padded smem
    float* row = &red[w][lane][0];
    #pragma unroll
    for (int q = 0; q < 4; q++) {
        row[4 * q + 0] = p[q].x; row[4 * q + 1] = p[q].y;
        row[4 * q + 2] = p[q].z; row[4 * q + 3] = p[q].w;
    }
    __syncwarp();
    int c = lane & 15;                     // lanes 16-31 duplicate channels 0-15
    float h2 = 0.f;
    #pragma unroll 8
    for (int l = 0; l < 32; l++) h2 += red[w][l][c];

    float ps = h2 * s_a2[c], pd = h2 * s_a2[16 + c];
    #pragma unroll
    for (int off = 8; off; off >>= 1) {
        ps += __shfl_xor_sync(0xFFFFFFFFu, ps, off);
        pd += __shfl_xor_sync(0xFFFFFFFFu, pd, off);
    }
    if (lane < 16) g_h2[d * 16 + lane] = h2;
    if (lane == 0) { g_as2[d] = ps; g_ad2[d] = pd; }
}

// ---------------- layer 2 aggregation -> output ----------------------------------
__global__ void __launch_bounds__(256) k_agg2(const float* __restrict__ b2,
                                              float* __restrict__ out) {
    int t = blockIdx.x * blockDim.x + threadIdx.x;
    int node = t >> 4, c = t & 15;
    if (node >= NN) return;
    int beg = g_rowptr[node], end = g_rowptr[node + 1];
    float adv = g_ad2[node];
    float acc = 0.f, den = 0.f;
    for (int j = beg; j < end; j++) {
        int s = g_col[j];
        float e = g_as2[s] + adv;
        e = e > 0.f ? e : 0.2f * e;
        float ex = __expf(e);
        den += ex;
        acc += ex * g_h2[s * 16 + c];
    }
    out[node * 16 + c] = acc / (den + 1e-16f) + b2[c];
}

// ---------------- launch (single stream, serial — R3 skeleton) -------------------
extern "C" void kernel_launch(void* const* d_in, const int* in_sizes, int n_in,
                              void* d_out, int out_size) {
    const float* x    = (const float*)d_in[0];
    const int*   ei   = (const int*)d_in[1];
    const float* W1   = (const float*)d_in[2];
    const float* as1w = (const float*)d_in[3];
    const float* ad1w = (const float*)d_in[4];
    const float* b1   = (const float*)d_in[5];
    const float* W2   = (const float*)d_in[6];
    const float* as2w = (const float*)d_in[7];
    const float* ad2w = (const float*)d_in[8];
    const float* b2   = (const float*)d_in[9];
    float* out = (float*)d_out;

    static bool s_init = false;
    if (!s_init) {
        cudaFuncSetAttribute(k_fused1, cudaFuncAttributeMaxDynamicSharedMemorySize, 69632);
        s_init = true;
    }

    // deg histogram overlapped with layer-1 GEMM (one grid, intra-kernel overlap)
    k_fused1<<<DEGB + GEMMB, 128, 69632>>>(x, W1, as1w, ad1w, ei);

    // CSR build
    k_scanall<<<NSCAN, 1024>>>();
    k_scatter<<<(EE / 4 + NN + 255) / 256, 256>>>(ei);

    // fused layer-1 aggregation + layer-2 linear
    k_agg1g2<<<(NN + 7) / 8, 256>>>(b1, W2, as2w, ad2w);

    // layer-2 aggregation -> output
    k_agg2<<<(NN * 16 + 255) / 256, 256>>>(b2, out);
}

// round 6
// speedup vs baseline: 1.2603x; 1.2537x over previous
#include <cuda_runtime.h>
#include <cuda_fp16.h>

#define NN 50000
#define EE 800000
#define TE 850000          // EE + NN self-loops
#define DEGB 96            // blocks of fused kernel doing degree counting
#define GEMMB 444          // blocks of fused kernel doing gemm1 (3/SM * 148)
#define NSCAN 49           // ceil(NN/1024)

typedef unsigned long long ull;

// ---------------- scratch (static device globals; zero-initialized) --------------
__device__ unsigned g_h1h[NN * 64];   // layer-1 linear output, fp16 (128 half/row)
__device__ float g_hout[NN * 128];    // layer-1 aggregated + ELU (fp32)
__device__ float g_as1[NN * 8];
__device__ float g_ad1[NN * 8];
__device__ float g_h2[NN * 16];
__device__ float g_as2[NN];
__device__ float g_ad2[NN];
__device__ int   g_deg[NN];           // zero at entry of every call (invariant)
__device__ int   g_rowptr[NN + 1];
__device__ int   g_cursor[NN];
__device__ int   g_col[TE];
__device__ int   g_bsum[NSCAN];
__device__ int   g_boff[NSCAN];

// ---------------- packed f32x2 helpers (sm_100+ FFMA2) ----------------
__device__ __forceinline__ ull ffma2(ull a, ull b, ull c) {
    ull d;
    asm("fma.rn.f32x2 %0, %1, %2, %3;" : "=l"(d) : "l"(a), "l"(b), "l"(c));
    return d;
}
__device__ __forceinline__ ull packdup(float x) {
    ull v;
    asm("mov.b64 %0, {%1, %1};" : "=l"(v) : "f"(x));
    return v;
}
__device__ __forceinline__ float2 unpack2(ull v) {
    float2 f;
    asm("mov.b64 {%0, %1}, %2;" : "=f"(f.x), "=f"(f.y) : "l"(v));
    return f;
}

// ---------------- fused: degree histogram (blocks 0..DEGB) + gemm1 (rest) --------
__global__ void __launch_bounds__(128) k_fused1(
    const float* __restrict__ x, const float* __restrict__ W1,
    const float* __restrict__ asw, const float* __restrict__ adw,
    const int* __restrict__ ei)
{
    extern __shared__ float sm[];
    if (blockIdx.x < DEGB) {
        const int nt = DEGB * 128;
        int t = blockIdx.x * 128 + threadIdx.x;
        const int4* dsts = (const int4*)(ei + EE);
        for (int i = t; i < EE / 4; i += nt) {
            int4 d = dsts[i];
            atomicAdd(&g_deg[d.x], 1);
            atomicAdd(&g_deg[d.y], 1);
            atomicAdd(&g_deg[d.z], 1);
            atomicAdd(&g_deg[d.w], 1);
        }
        return;
    }
    float* Ws = sm;            // 128*128
    float* xs = sm + 16384;    // 8*128
    int tid = threadIdx.x, lane = tid & 31, w = tid >> 5;

    for (int i = tid; i < 16384; i += 128) Ws[i] = W1[i];
    float4 aws = ((const float4*)asw)[lane];
    float4 awd = ((const float4*)adw)[lane];
    __syncthreads();

    int bid = blockIdx.x - DEGB;
    for (int chunk = bid; chunk < NN / 8; chunk += GEMMB) {
        int base = chunk * 8;
        for (int i = tid; i < 1024; i += 128) xs[i] = x[base * 128 + i];
        __syncthreads();

        int r0 = 2 * w;
        const float* x0p = xs + r0 * 128;
        const float* x1p = x0p + 128;
        ull a00 = 0, a01 = 0, a10 = 0, a11 = 0;
        #pragma unroll 4
        for (int k = 0; k < 128; k++) {
            ulonglong2 wv = *(const ulonglong2*)(Ws + k * 128 + lane * 4);
            ull xp0 = packdup(x0p[k]);
            ull xp1 = packdup(x1p[k]);
            a00 = ffma2(xp0, wv.x, a00);
            a01 = ffma2(xp0, wv.y, a01);
            a10 = ffma2(xp1, wv.x, a10);
            a11 = ffma2(xp1, wv.y, a11);
        }
        #pragma unroll
        for (int rr = 0; rr < 2; rr++) {
            float2 lo = unpack2(rr == 0 ? a00 : a10);
            float2 hi = unpack2(rr == 0 ? a01 : a11);
            int g = base + r0 + rr;
            __half2 p0 = __floats2half2_rn(lo.x, lo.y);
            __half2 p1 = __floats2half2_rn(hi.x, hi.y);
            uint2 u;
            u.x = *reinterpret_cast<unsigned*>(&p0);
            u.y = *reinterpret_cast<unsigned*>(&p1);
            ((uint2*)g_h1h)[g * 32 + lane] = u;
            float ps = lo.x * aws.x + lo.y * aws.y + hi.x * aws.z + hi.y * aws.w;
            float pd = lo.x * awd.x + lo.y * awd.y + hi.x * awd.z + hi.y * awd.w;
            ps += __shfl_xor_sync(0xFFFFFFFFu, ps, 1);
            ps += __shfl_xor_sync(0xFFFFFFFFu, ps, 2);
            pd += __shfl_xor_sync(0xFFFFFFFFu, pd, 1);
            pd += __shfl_xor_sync(0xFFFFFFFFu, pd, 2);
            if ((lane & 3) == 0) {
                g_as1[g * 8 + (lane >> 2)] = ps;
                g_ad1[g * 8 + (lane >> 2)] = pd;
            }
        }
        __syncthreads();
    }
}

// ---------------- 3-phase scan: rowptr from deg (+1 self-loop each) --------------
__global__ void k_scan1() {
    __shared__ int ws[32];
    int t = threadIdx.x, lane = t & 31, wid = t >> 5;
    int i = blockIdx.x * 1024 + t;
    int v = (i < NN) ? g_deg[i] + 1 : 0;
    #pragma unroll
    for (int o = 16; o; o >>= 1) v += __shfl_xor_sync(0xFFFFFFFFu, v, o);
    if (lane == 0) ws[wid] = v;
    __syncthreads();
    if (wid == 0) {
        int s = ws[lane];
        #pragma unroll
        for (int o = 16; o; o >>= 1) s += __shfl_xor_sync(0xFFFFFFFFu, s, o);
        if (lane == 0) g_bsum[blockIdx.x] = s;
    }
}

__global__ void k_scan2() {
    if (threadIdx.x == 0) {
        int run = 0;
        #pragma unroll 1
        for (int j = 0; j < NSCAN; j++) { int v = g_bsum[j]; g_boff[j] = run; run += v; }
        g_rowptr[NN] = run;   // == TE
    }
}

__global__ void k_scan3() {
    __shared__ int warpsums[32];
    int t = threadIdx.x, lane = t & 31, wid = t >> 5;
    int i = blockIdx.x * 1024 + t;
    int v = (i < NN) ? g_deg[i] + 1 : 0;
    int x = v;
    #pragma unroll
    for (int o = 1; o < 32; o <<= 1) {
        int y = __shfl_up_sync(0xFFFFFFFFu, x, o);
        if (lane >= o) x += y;
    }
    if (lane == 31) warpsums[wid] = x;
    __syncthreads();
    if (wid == 0) {
        int w2 = warpsums[lane];
        #pragma unroll
        for (int o = 1; o < 32; o <<= 1) {
            int y = __shfl_up_sync(0xFFFFFFFFu, w2, o);
            if (lane >= o) w2 += y;
        }
        warpsums[lane] = w2;
    }
    __syncthreads();
    int excl = x - v + (wid > 0 ? warpsums[wid - 1] : 0) + g_boff[blockIdx.x];
    if (i < NN) {
        g_rowptr[i] = excl;
        g_cursor[i] = excl;
        g_deg[i] = 0;          // restore invariant for the next call
    }
}

// ---------------- scatter edges into CSR (by destination), int4-vectorized -------
__global__ void __launch_bounds__(256) k_scatter(const int* __restrict__ ei) {
    int t = blockIdx.x * blockDim.x + threadIdx.x;
    const int Q = EE / 4;   // 200000
    if (t < Q) {
        int4 s4 = ((const int4*)ei)[t];
        int4 d4 = ((const int4*)(ei + EE))[t];
        g_col[atomicAdd(&g_cursor[d4.x], 1)] = s4.x;
        g_col[atomicAdd(&g_cursor[d4.y], 1)] = s4.y;
        g_col[atomicAdd(&g_cursor[d4.z], 1)] = s4.z;
        g_col[atomicAdd(&g_cursor[d4.w], 1)] = s4.w;
    } else {
        int n = t - Q;
        if (n < NN) g_col[atomicAdd(&g_cursor[n], 1)] = n;   // self-loop
    }
}

// ---------------- layer 1 aggregation (dual-stream half-warp edition) ------------
// One warp per dst node. Two edge streams: half-warp q processes edges beg+q,
// beg+q+2, ... Lane covers 8 fp16 channels via one uint4 (LDG.128): half the
// LDG count of the uint2 version, 2 independent chains -> ~2x MLP.
__global__ void __launch_bounds__(256) k_agg1(const float* __restrict__ b1) {
    int warp = (blockIdx.x * blockDim.x + threadIdx.x) >> 5;
    int lane = threadIdx.x & 31;
    if (warp >= NN) return;
    int d = warp;
    int half = lane >> 4;          // edge stream id (0/1)
    int hl = lane & 15;            // lane within half: channels [8*hl, 8*hl+8)
    int head = hl >> 1;            // 16 channels per head -> 2 lanes per head
    int beg = g_rowptr[d], end = g_rowptr[d + 1];
    float adv = g_ad1[d * 8 + head];
    const uint4* h1v = (const uint4*)g_h1h;   // 16 uint4 per 256B row

    float4 accA = make_float4(0.f, 0.f, 0.f, 0.f);
    float4 accB = make_float4(0.f, 0.f, 0.f, 0.f);
    float den = 0.f;
    #pragma unroll 2
    for (int j = beg + half; j < end; j += 2) {
        int s = g_col[j];
        float e = g_as1[s * 8 + head] + adv;
        e = e > 0.f ? e : 0.2f * e;
        float ex = __expf(e);
        den += ex;
        uint4 hv = h1v[s * 16 + hl];
        float2 f0 = __half22float2(*reinterpret_cast<__half2*>(&hv.x));
        float2 f1 = __half22float2(*reinterpret_cast<__half2*>(&hv.y));
        float2 f2 = __half22float2(*reinterpret_cast<__half2*>(&hv.z));
        float2 f3 = __half22float2(*reinterpret_cast<__half2*>(&hv.w));
        accA.x += ex * f0.x; accA.y += ex * f0.y;
        accA.z += ex * f1.x; accA.w += ex * f1.y;
        accB.x += ex * f2.x; accB.y += ex * f2.y;
        accB.z += ex * f3.x; accB.w += ex * f3.y;
    }
    // merge the two edge streams (channel layout identical across halves)
    den   += __shfl_xor_sync(0xFFFFFFFFu, den,   16);
    accA.x += __shfl_xor_sync(0xFFFFFFFFu, accA.x, 16);
    accA.y += __shfl_xor_sync(0xFFFFFFFFu, accA.y, 16);
    accA.z += __shfl_xor_sync(0xFFFFFFFFu, accA.z, 16);
    accA.w += __shfl_xor_sync(0xFFFFFFFFu, accA.w, 16);
    accB.x += __shfl_xor_sync(0xFFFFFFFFu, accB.x, 16);
    accB.y += __shfl_xor_sync(0xFFFFFFFFu, accB.y, 16);
    accB.z += __shfl_xor_sync(0xFFFFFFFFu, accB.z, 16);
    accB.w += __shfl_xor_sync(0xFFFFFFFFu, accB.w, 16);

    float inv = 1.f / (den + 1e-16f);
    // bias + ELU; halves now hold identical data -> split the stores
    float4 bA = ((const float4*)b1)[2 * hl];
    float4 bB = ((const float4*)b1)[2 * hl + 1];
    float4 oA, oB;
    oA.x = accA.x * inv + bA.x; oA.x = oA.x > 0.f ? oA.x : expm1f(oA.x);
    oA.y = accA.y * inv + bA.y; oA.y = oA.y > 0.f ? oA.y : expm1f(oA.y);
    oA.z = accA.z * inv + bA.z; oA.z = oA.z > 0.f ? oA.z : expm1f(oA.z);
    oA.w = accA.w * inv + bA.w; oA.w = oA.w > 0.f ? oA.w : expm1f(oA.w);
    oB.x = accB.x * inv + bB.x; oB.x = oB.x > 0.f ? oB.x : expm1f(oB.x);
    oB.y = accB.y * inv + bB.y; oB.y = oB.y > 0.f ? oB.y : expm1f(oB.y);
    oB.z = accB.z * inv + bB.z; oB.z = oB.z > 0.f ? oB.z : expm1f(oB.z);
    oB.w = accB.w * inv + bB.w; oB.w = oB.w > 0.f ? oB.w : expm1f(oB.w);
    ((float4*)g_hout)[d * 32 + 2 * hl + half] = half ? oB : oA;
    ((float4*)g_hout)[d * 32 + 2 * hl + (half ^ 1)] = half ? oA : oB;
}

// ---------------- layer 2: linear + alphas ----------------
__global__ void __launch_bounds__(128) k_gemm2(
    const float* __restrict__ W2, const float* __restrict__ as2w,
    const float* __restrict__ ad2w)
{
    __shared__ float Ws[128 * 16];
    __shared__ float xs[8][128];
    __shared__ float s_as[16], s_ad[16];
    int tid = threadIdx.x;
    for (int i = tid; i < 2048; i += 128) Ws[i] = W2[i];
    if (tid < 16) { s_as[tid] = as2w[tid]; s_ad[tid] = ad2w[tid]; }
    __syncthreads();

    int row8 = tid >> 4, c = tid & 15;
    for (int chunk = blockIdx.x; chunk < NN / 8; chunk += gridDim.x) {
        int base = chunk * 8;
        for (int i = tid; i < 1024; i += 128) xs[i >> 7][i & 127] = g_hout[base * 128 + i];
        __syncthreads();
        float acc = 0.f;
        #pragma unroll 8
        for (int k = 0; k < 128; k++) acc += xs[row8][k] * Ws[k * 16 + c];
        int r = base + row8;
        g_h2[r * 16 + c] = acc;
        float ps = acc * s_as[c], pd = acc * s_ad[c];
        #pragma unroll
        for (int o = 8; o; o >>= 1) {
            ps += __shfl_xor_sync(0xFFFFFFFFu, ps, o);
            pd += __shfl_xor_sync(0xFFFFFFFFu, pd, o);
        }
        if (c == 0) { g_as2[r] = ps; g_ad2[r] = pd; }
        __syncthreads();
    }
}

// ---------------- layer 2 aggregation -> output ----------------------------------
__global__ void __launch_bounds__(256) k_agg2(const float* __restrict__ b2,
                                              float* __restrict__ out) {
    int t = blockIdx.x * blockDim.x + threadIdx.x;
    int node = t >> 4, c = t & 15;
    if (node >= NN) return;
    int beg = g_rowptr[node], end = g_rowptr[node + 1];
    float adv = g_ad2[node];
    float acc = 0.f, den = 0.f;
    for (int j = beg; j < end; j++) {
        int s = g_col[j];
        float e = g_as2[s] + adv;
        e = e > 0.f ? e : 0.2f * e;
        float ex = __expf(e);
        den += ex;
        acc += ex * g_h2[s * 16 + c];
    }
    out[node * 16 + c] = acc / (den + 1e-16f) + b2[c];
}

// ---------------- launch (R3 skeleton, single stream) ----------------------------
extern "C" void kernel_launch(void* const* d_in, const int* in_sizes, int n_in,
                              void* d_out, int out_size) {
    const float* x    = (const float*)d_in[0];
    const int*   ei   = (const int*)d_in[1];
    const float* W1   = (const float*)d_in[2];
    const float* as1w = (const float*)d_in[3];
    const float* ad1w = (const float*)d_in[4];
    const float* b1   = (const float*)d_in[5];
    const float* W2   = (const float*)d_in[6];
    const float* as2w = (const float*)d_in[7];
    const float* ad2w = (const float*)d_in[8];
    const float* b2   = (const float*)d_in[9];
    float* out = (float*)d_out;

    static bool s_init = false;
    if (!s_init) {
        cudaFuncSetAttribute(k_fused1, cudaFuncAttributeMaxDynamicSharedMemorySize, 69632);
        s_init = true;
    }

    // deg histogram overlapped with layer-1 GEMM (one grid, intra-kernel overlap)
    k_fused1<<<DEGB + GEMMB, 128, 69632>>>(x, W1, as1w, ad1w, ei);

    // CSR build
    k_scan1<<<NSCAN, 1024>>>();
    k_scan2<<<1, 32>>>();
    k_scan3<<<NSCAN, 1024>>>();
    k_scatter<<<(EE / 4 + NN + 255) / 256, 256>>>(ei);

    // Layer 1 aggregation (dual-stream)
    k_agg1<<<(NN * 32 + 255) / 256, 256>>>(b1);

    // Layer 2
    k_gemm2<<<888, 128>>>(W2, as2w, ad2w);
    k_agg2<<<(NN * 16 + 255) / 256, 256>>>(b2, out);
}